// round 8
// baseline (speedup 1.0000x reference)
#include <cuda_runtime.h>

// x[B=2, F=12, C=64, H=256, W=256] fp32 NCHW, pad=1 -> out [2,12,64,258,258]

#define B_ 2
#define F_ 12
#define C_ 64
#define H_ 256
#define P_ 1

#define HO_ (H_ + 2 * P_)          // 258
#define PLANE_IN (H_ * H_)         // 65536
#define PLANE_OUT (HO_ * HO_)      // 66564
#define NPLANES (B_ * F_ * C_)     // 1536

#define BULK_BLOCKS 32             // 32 blocks * 8 warps = 256 rows; warp = one row
#define HALO_ELEMS 1028
#define HALO_BLOCKS 5
#define TOTAL_BLOCKS (BULK_BLOCKS + HALO_BLOCKS)

__device__ __forceinline__ float hpx_fetch(const float* __restrict__ in,
                                           int plane, int f, int nf, int rot,
                                           int i, int j) {
    int yy, xx;
    switch (rot) {
        case 0: yy = i;           xx = j;           break;
        case 1: yy = j;           xx = H_ - 1 - i;  break;
        case 2: yy = H_ - 1 - i;  xx = H_ - 1 - j;  break;
        default: yy = H_ - 1 - j; xx = i;           break;
    }
    return in[(plane + (nf - f) * C_) * PLANE_IN + yy * H_ + xx];
}

// Value of halo output element (plane, yo, xo). (yo,xo) guaranteed non-interior.
__device__ float hpx_halo_value(const float* __restrict__ in, int plane, int yo, int xo) {
    const int y = yo - P_;
    const int x = xo - P_;

    const int f = (plane >> 6) % F_;
    const int i = f & 3;
    const int cls = f >> 2;

    const int ry = (y < 0) ? 0 : (y < H_ ? 1 : 2);
    const int rx = (x < 0) ? 0 : (x < H_ ? 1 : 2);
    const int reg = ry * 3 + rx;
    const int ti = (ry == 0) ? H_ + y : (ry == 1 ? y : y - H_);
    const int tj = (rx == 0) ? H_ + x : (rx == 1 ? x : x - H_);

    int nf = f, rot = 0;

    if (cls == 0) {
        switch (reg) {
            case 0: nf = (i + 2) & 3; rot = 2; break;
            case 1: nf = (i + 1) & 3; rot = 1; break;
            case 2: nf = (i + 1) & 3; rot = 3; break;
            case 3: nf = (i + 3) & 3;          break;
            case 5: nf = ((i + 1) & 3) + 4;    break;
            case 6: nf = (i + 3) & 3;          break;
            case 7: nf = i + 4;                break;
            default: nf = i + 8;               break;
        }
    } else if (cls == 1) {
        switch (reg) {
            case 0: {  // tri-point TL
                const int ic = ti - (H_ - P_), jc = tj - (H_ - P_);
                const int nt = i, nl = (i + 3) & 3;
                if (ic == P_ - 1 && jc == P_ - 1)
                    return 0.5f * (hpx_fetch(in, plane, f, nt, 0, H_ - 1, 0) +
                                   hpx_fetch(in, plane, f, nl, 0, 0, H_ - 1));
                if (jc == P_ - 1) return hpx_fetch(in, plane, f, nt, 0, ti, 0);
                if (ic == P_ - 1) return hpx_fetch(in, plane, f, nl, 0, 0, tj);
                return 0.0f;
            }
            case 1: nf = i;                 break;
            case 2: nf = (i + 1) & 3;       break;
            case 3: nf = (i + 3) & 3;       break;
            case 5: nf = ((i + 1) & 3) + 4; break;
            case 6: nf = ((i + 3) & 3) + 4; break;
            case 7: nf = i + 8;             break;
            default: {  // tri-point BR
                const int nb = i + 8, nr = ((i + 1) & 3) + 4;
                if (ti == 0 && tj == 0)
                    return 0.5f * (hpx_fetch(in, plane, f, nb, 0, 0, H_ - 1) +
                                   hpx_fetch(in, plane, f, nr, 0, H_ - 1, 0));
                if (tj == 0) return hpx_fetch(in, plane, f, nb, 0, ti, H_ - 1);
                if (ti == 0) return hpx_fetch(in, plane, f, nr, 0, H_ - 1, tj);
                return 0.0f;
            }
        }
    } else {
        switch (reg) {
            case 0: nf = i;                           break;
            case 1: nf = i + 4;                       break;
            case 2: nf = ((i + 1) & 3) + 4;           break;
            case 3: nf = ((i + 3) & 3) + 4;           break;
            case 5: nf = ((i + 1) & 3) + 8;           break;
            case 6: nf = ((i + 3) & 3) + 8; rot = 3;  break;
            case 7: nf = ((i + 3) & 3) + 8; rot = 1;  break;
            default: nf = ((i + 3) & 3) + 8; rot = 2; break;
        }
    }
    return hpx_fetch(in, plane, f, nf, rot, ti, tj);
}

__global__ void __launch_bounds__(256) hpx_pad_kernel(const float* __restrict__ in,
                                                      float* __restrict__ out) {
    const int plane = blockIdx.y;

    if (blockIdx.x < BULK_BLOCKS) {
        // ── Bulk: one warp = one input row. Each thread: 2 adjacent LDG.128 (32 B
        //    contiguous), 8 contiguous scalar stores. Warp streams are fully
        //    contiguous: 1 KB read run, 1 KB write run per row. ──
        const int warp = threadIdx.x >> 5;
        const int lane = threadIdx.x & 31;
        const int row = (blockIdx.x << 3) + warp;               // 0..255

        const float4* src = reinterpret_cast<const float4*>(in + plane * PLANE_IN) + (row << 6);
        const float4 v0 = src[lane * 2 + 0];
        const float4 v1 = src[lane * 2 + 1];

        float* o = out + plane * PLANE_OUT + (row + P_) * HO_ + P_ + (lane << 3);
        o[0] = v0.x; o[1] = v0.y; o[2] = v0.z; o[3] = v0.w;
        o[4] = v1.x; o[5] = v1.y; o[6] = v1.z; o[7] = v1.w;
    } else {
        // ── Halo: 1028 elements per plane ──
        const int h = ((blockIdx.x - BULK_BLOCKS) << 8) + threadIdx.x;
        if (h >= HALO_ELEMS) return;
        int yo, xo;
        if (h < HO_) {
            yo = 0;        xo = h;
        } else if (h < 2 * HO_) {
            yo = HO_ - 1;  xo = h - HO_;
        } else if (h < 2 * HO_ + H_) {
            yo = h - 2 * HO_ + 1;          xo = 0;
        } else {
            yo = h - (2 * HO_ + H_) + 1;   xo = HO_ - 1;
        }
        out[plane * PLANE_OUT + yo * HO_ + xo] = hpx_halo_value(in, plane, yo, xo);
    }
}

extern "C" void kernel_launch(void* const* d_in, const int* in_sizes, int n_in,
                              void* d_out, int out_size) {
    const float* x = (const float*)d_in[0];
    float* out = (float*)d_out;
    (void)in_sizes; (void)n_in; (void)out_size;

    dim3 block(256);
    dim3 grid(TOTAL_BLOCKS, NPLANES);   // 37 x 1536
    hpx_pad_kernel<<<grid, block>>>(x, out);
}

// round 9
// speedup vs baseline: 2.6506x; 2.6506x over previous
#include <cuda_runtime.h>

// x[B=2, F=12, C=64, H=256, W=256] fp32 NCHW, pad=1 -> out [2,12,64,258,258]

#define B_ 2
#define F_ 12
#define C_ 64
#define H_ 256
#define P_ 1

#define HO_ (H_ + 2 * P_)          // 258
#define PLANE_IN (H_ * H_)         // 65536
#define PLANE_OUT (HO_ * HO_)      // 66564
#define NPLANES (B_ * F_ * C_)     // 1536

#define BULK_BLOCKS 32             // 32 blocks * 8 warps = 256 rows; warp = one row
#define HALO_ELEMS 1028
#define HALO_BLOCKS 5
#define TOTAL_BLOCKS (BULK_BLOCKS + HALO_BLOCKS)

__device__ __forceinline__ float hpx_fetch(const float* __restrict__ in,
                                           int plane, int f, int nf, int rot,
                                           int i, int j) {
    int yy, xx;
    switch (rot) {
        case 0: yy = i;           xx = j;           break;
        case 1: yy = j;           xx = H_ - 1 - i;  break;
        case 2: yy = H_ - 1 - i;  xx = H_ - 1 - j;  break;
        default: yy = H_ - 1 - j; xx = i;           break;
    }
    return in[(plane + (nf - f) * C_) * PLANE_IN + yy * H_ + xx];
}

// Value of halo output element (plane, yo, xo). (yo,xo) guaranteed non-interior.
__device__ float hpx_halo_value(const float* __restrict__ in, int plane, int yo, int xo) {
    const int y = yo - P_;
    const int x = xo - P_;

    const int f = (plane >> 6) % F_;
    const int i = f & 3;
    const int cls = f >> 2;

    const int ry = (y < 0) ? 0 : (y < H_ ? 1 : 2);
    const int rx = (x < 0) ? 0 : (x < H_ ? 1 : 2);
    const int reg = ry * 3 + rx;
    const int ti = (ry == 0) ? H_ + y : (ry == 1 ? y : y - H_);
    const int tj = (rx == 0) ? H_ + x : (rx == 1 ? x : x - H_);

    int nf = f, rot = 0;

    if (cls == 0) {
        switch (reg) {
            case 0: nf = (i + 2) & 3; rot = 2; break;
            case 1: nf = (i + 1) & 3; rot = 1; break;
            case 2: nf = (i + 1) & 3; rot = 3; break;
            case 3: nf = (i + 3) & 3;          break;
            case 5: nf = ((i + 1) & 3) + 4;    break;
            case 6: nf = (i + 3) & 3;          break;
            case 7: nf = i + 4;                break;
            default: nf = i + 8;               break;
        }
    } else if (cls == 1) {
        switch (reg) {
            case 0: {  // tri-point TL
                const int ic = ti - (H_ - P_), jc = tj - (H_ - P_);
                const int nt = i, nl = (i + 3) & 3;
                if (ic == P_ - 1 && jc == P_ - 1)
                    return 0.5f * (hpx_fetch(in, plane, f, nt, 0, H_ - 1, 0) +
                                   hpx_fetch(in, plane, f, nl, 0, 0, H_ - 1));
                if (jc == P_ - 1) return hpx_fetch(in, plane, f, nt, 0, ti, 0);
                if (ic == P_ - 1) return hpx_fetch(in, plane, f, nl, 0, 0, tj);
                return 0.0f;
            }
            case 1: nf = i;                 break;
            case 2: nf = (i + 1) & 3;       break;
            case 3: nf = (i + 3) & 3;       break;
            case 5: nf = ((i + 1) & 3) + 4; break;
            case 6: nf = ((i + 3) & 3) + 4; break;
            case 7: nf = i + 8;             break;
            default: {  // tri-point BR
                const int nb = i + 8, nr = ((i + 1) & 3) + 4;
                if (ti == 0 && tj == 0)
                    return 0.5f * (hpx_fetch(in, plane, f, nb, 0, 0, H_ - 1) +
                                   hpx_fetch(in, plane, f, nr, 0, H_ - 1, 0));
                if (tj == 0) return hpx_fetch(in, plane, f, nb, 0, ti, H_ - 1);
                if (ti == 0) return hpx_fetch(in, plane, f, nr, 0, H_ - 1, tj);
                return 0.0f;
            }
        }
    } else {
        switch (reg) {
            case 0: nf = i;                           break;
            case 1: nf = i + 4;                       break;
            case 2: nf = ((i + 1) & 3) + 4;           break;
            case 3: nf = ((i + 3) & 3) + 4;           break;
            case 5: nf = ((i + 1) & 3) + 8;           break;
            case 6: nf = ((i + 3) & 3) + 8; rot = 3;  break;
            case 7: nf = ((i + 3) & 3) + 8; rot = 1;  break;
            default: nf = ((i + 3) & 3) + 8; rot = 2; break;
        }
    }
    return hpx_fetch(in, plane, f, nf, rot, ti, tj);
}

__global__ void __launch_bounds__(256) hpx_pad_kernel(const float* __restrict__ in,
                                                      float* __restrict__ out) {
    const int plane = blockIdx.y;

    if (blockIdx.x < BULK_BLOCKS) {
        // ── Bulk: one warp = one input row, warp-coalesced halves.
        //    Lane loads float4 #(lane) and #(lane+32) of the row: each LDG.128
        //    instruction covers 32 consecutive float4s (512 B run), front-batched
        //    MLP=2. Warp footprint = one contiguous 1 KB run in and out. ──
        const int warp = threadIdx.x >> 5;
        const int lane = threadIdx.x & 31;
        const int row = (blockIdx.x << 3) + warp;               // 0..255

        const float4* src = reinterpret_cast<const float4*>(in + plane * PLANE_IN) + (row << 6);
        const float4 v0 = src[lane];
        const float4 v1 = src[lane + 32];

        float* o = out + plane * PLANE_OUT + (row + P_) * HO_ + P_;
        float* o0 = o + (lane << 2);
        o0[0] = v0.x; o0[1] = v0.y; o0[2] = v0.z; o0[3] = v0.w;
        float* o1 = o + 128 + (lane << 2);
        o1[0] = v1.x; o1[1] = v1.y; o1[2] = v1.z; o1[3] = v1.w;
    } else {
        // ── Halo: 1028 elements per plane ──
        const int h = ((blockIdx.x - BULK_BLOCKS) << 8) + threadIdx.x;
        if (h >= HALO_ELEMS) return;
        int yo, xo;
        if (h < HO_) {
            yo = 0;        xo = h;
        } else if (h < 2 * HO_) {
            yo = HO_ - 1;  xo = h - HO_;
        } else if (h < 2 * HO_ + H_) {
            yo = h - 2 * HO_ + 1;          xo = 0;
        } else {
            yo = h - (2 * HO_ + H_) + 1;   xo = HO_ - 1;
        }
        out[plane * PLANE_OUT + yo * HO_ + xo] = hpx_halo_value(in, plane, yo, xo);
    }
}

extern "C" void kernel_launch(void* const* d_in, const int* in_sizes, int n_in,
                              void* d_out, int out_size) {
    const float* x = (const float*)d_in[0];
    float* out = (float*)d_out;
    (void)in_sizes; (void)n_in; (void)out_size;

    dim3 block(256);
    dim3 grid(TOTAL_BLOCKS, NPLANES);   // 37 x 1536
    hpx_pad_kernel<<<grid, block>>>(x, out);
}

// round 13
// speedup vs baseline: 2.7742x; 1.0467x over previous
#include <cuda_runtime.h>

// x[B=2, F=12, C=64, H=256, W=256] fp32 NCHW, pad=1 -> out [2,12,64,258,258]

#define B_ 2
#define F_ 12
#define C_ 64
#define H_ 256
#define P_ 1

#define HO_ (H_ + 2 * P_)          // 258
#define PLANE_IN (H_ * H_)         // 65536
#define PLANE_OUT (HO_ * HO_)      // 66564
#define NPLANES (B_ * F_ * C_)     // 1536

#define BULK_BLOCKS 32             // 32 blocks * 8 warps = 256 rows; warp = one row
#define HALO_ELEMS 1028
#define HALO_BLOCKS 5
#define TOTAL_BLOCKS (BULK_BLOCKS + HALO_BLOCKS)

__device__ __forceinline__ float hpx_fetch(const float* __restrict__ in,
                                           int plane, int f, int nf, int rot,
                                           int i, int j) {
    int yy, xx;
    switch (rot) {
        case 0: yy = i;           xx = j;           break;
        case 1: yy = j;           xx = H_ - 1 - i;  break;
        case 2: yy = H_ - 1 - i;  xx = H_ - 1 - j;  break;
        default: yy = H_ - 1 - j; xx = i;           break;
    }
    return in[(plane + (nf - f) * C_) * PLANE_IN + yy * H_ + xx];
}

// Value of halo output element (plane, yo, xo). (yo,xo) guaranteed non-interior.
__device__ float hpx_halo_value(const float* __restrict__ in, int plane, int yo, int xo) {
    const int y = yo - P_;
    const int x = xo - P_;

    const int f = (plane >> 6) % F_;
    const int i = f & 3;
    const int cls = f >> 2;

    const int ry = (y < 0) ? 0 : (y < H_ ? 1 : 2);
    const int rx = (x < 0) ? 0 : (x < H_ ? 1 : 2);
    const int reg = ry * 3 + rx;
    const int ti = (ry == 0) ? H_ + y : (ry == 1 ? y : y - H_);
    const int tj = (rx == 0) ? H_ + x : (rx == 1 ? x : x - H_);

    int nf = f, rot = 0;

    if (cls == 0) {
        switch (reg) {
            case 0: nf = (i + 2) & 3; rot = 2; break;
            case 1: nf = (i + 1) & 3; rot = 1; break;
            case 2: nf = (i + 1) & 3; rot = 3; break;
            case 3: nf = (i + 3) & 3;          break;
            case 5: nf = ((i + 1) & 3) + 4;    break;
            case 6: nf = (i + 3) & 3;          break;
            case 7: nf = i + 4;                break;
            default: nf = i + 8;               break;
        }
    } else if (cls == 1) {
        switch (reg) {
            case 0: {  // tri-point TL
                const int ic = ti - (H_ - P_), jc = tj - (H_ - P_);
                const int nt = i, nl = (i + 3) & 3;
                if (ic == P_ - 1 && jc == P_ - 1)
                    return 0.5f * (hpx_fetch(in, plane, f, nt, 0, H_ - 1, 0) +
                                   hpx_fetch(in, plane, f, nl, 0, 0, H_ - 1));
                if (jc == P_ - 1) return hpx_fetch(in, plane, f, nt, 0, ti, 0);
                if (ic == P_ - 1) return hpx_fetch(in, plane, f, nl, 0, 0, tj);
                return 0.0f;
            }
            case 1: nf = i;                 break;
            case 2: nf = (i + 1) & 3;       break;
            case 3: nf = (i + 3) & 3;       break;
            case 5: nf = ((i + 1) & 3) + 4; break;
            case 6: nf = ((i + 3) & 3) + 4; break;
            case 7: nf = i + 8;             break;
            default: {  // tri-point BR
                const int nb = i + 8, nr = ((i + 1) & 3) + 4;
                if (ti == 0 && tj == 0)
                    return 0.5f * (hpx_fetch(in, plane, f, nb, 0, 0, H_ - 1) +
                                   hpx_fetch(in, plane, f, nr, 0, H_ - 1, 0));
                if (tj == 0) return hpx_fetch(in, plane, f, nb, 0, ti, H_ - 1);
                if (ti == 0) return hpx_fetch(in, plane, f, nr, 0, H_ - 1, tj);
                return 0.0f;
            }
        }
    } else {
        switch (reg) {
            case 0: nf = i;                           break;
            case 1: nf = i + 4;                       break;
            case 2: nf = ((i + 1) & 3) + 4;           break;
            case 3: nf = ((i + 3) & 3) + 4;           break;
            case 5: nf = ((i + 1) & 3) + 8;           break;
            case 6: nf = ((i + 3) & 3) + 8; rot = 3;  break;
            case 7: nf = ((i + 3) & 3) + 8; rot = 1;  break;
            default: nf = ((i + 3) & 3) + 8; rot = 2; break;
        }
    }
    return hpx_fetch(in, plane, f, nf, rot, ti, tj);
}

__global__ void __launch_bounds__(256) hpx_pad_kernel(const float* __restrict__ in,
                                                      float* __restrict__ out) {
    // Schedule order is face-minor: y = (b*64 + c)*12 + f, so all 12 faces of a
    // (b,c) pair launch adjacently and halo gathers hit neighbor-face data in L2.
    // Memory plane index stays (b*12 + f)*64 + c.
    const int ys = blockIdx.y;
    const int f_sched = ys % 12;
    const int bc = ys / 12;                  // b*64 + c
    const int b = bc >> 6;
    const int c = bc & 63;
    const int plane = ((b * F_ + f_sched) << 6) + c;

    if (blockIdx.x < BULK_BLOCKS) {
        // ── Bulk: one warp = one input row, warp-coalesced halves, MLP=2 ──
        const int warp = threadIdx.x >> 5;
        const int lane = threadIdx.x & 31;
        const int row = (blockIdx.x << 3) + warp;               // 0..255

        const float4* src = reinterpret_cast<const float4*>(in + plane * PLANE_IN) + (row << 6);
        const float4 v0 = src[lane];
        const float4 v1 = src[lane + 32];

        float* o = out + plane * PLANE_OUT + (row + P_) * HO_ + P_;
        float* o0 = o + (lane << 2);
        o0[0] = v0.x; o0[1] = v0.y; o0[2] = v0.z; o0[3] = v0.w;
        float* o1 = o + 128 + (lane << 2);
        o1[0] = v1.x; o1[1] = v1.y; o1[2] = v1.z; o1[3] = v1.w;
    } else {
        // ── Halo: 1028 elements per plane ──
        const int h = ((blockIdx.x - BULK_BLOCKS) << 8) + threadIdx.x;
        if (h >= HALO_ELEMS) return;
        int yo, xo;
        if (h < HO_) {
            yo = 0;        xo = h;
        } else if (h < 2 * HO_) {
            yo = HO_ - 1;  xo = h - HO_;
        } else if (h < 2 * HO_ + H_) {
            yo = h - 2 * HO_ + 1;          xo = 0;
        } else {
            yo = h - (2 * HO_ + H_) + 1;   xo = HO_ - 1;
        }
        out[plane * PLANE_OUT + yo * HO_ + xo] = hpx_halo_value(in, plane, yo, xo);
    }
}

extern "C" void kernel_launch(void* const* d_in, const int* in_sizes, int n_in,
                              void* d_out, int out_size) {
    const float* x = (const float*)d_in[0];
    float* out = (float*)d_out;
    (void)in_sizes; (void)n_in; (void)out_size;

    dim3 block(256);
    dim3 grid(TOTAL_BLOCKS, NPLANES);   // 37 x 1536
    hpx_pad_kernel<<<grid, block>>>(x, out);
}